// round 15
// baseline (speedup 1.0000x reference)
#include <cuda_runtime.h>
#include <cstdint>

__device__ __forceinline__ uint32_t tf32u(float x) {
    uint32_t u; asm("cvt.rna.tf32.f32 %0, %1;" : "=r"(u) : "f"(x)); return u;
}
__device__ __forceinline__ float uaf(uint32_t u) { return __uint_as_float(u); }
__device__ __forceinline__ uint32_t fau(float f) { return __float_as_uint(f); }
__device__ __forceinline__ uint32_t s2u(const void* p) {
    uint32_t a;
    asm("{ .reg .u64 t; cvta.to.shared.u64 t, %1; cvt.u32.u64 %0, t; }"
        : "=r"(a) : "l"(p));
    return a;
}
__device__ __forceinline__ void cpasync16(uint32_t saddr, const void* g) {
    asm volatile("cp.async.ca.shared.global [%0], [%1], 16;"
                 :: "r"(saddr), "l"(g) : "memory");
}
#define CP_COMMIT() asm volatile("cp.async.commit_group;" ::: "memory")
#define CP_WAIT0() asm volatile("cp.async.wait_group 0;" ::: "memory")

#define MMA_TF32(c, a0, a1, a2, a3, b0, b1)                                   \
    asm volatile(                                                             \
        "mma.sync.aligned.m16n8k8.row.col.f32.tf32.tf32.f32 "                 \
        "{%0,%1,%2,%3},{%4,%5,%6,%7},{%8,%9},{%0,%1,%2,%3};"                  \
        : "+f"((c)[0]), "+f"((c)[1]), "+f"((c)[2]), "+f"((c)[3])              \
        : "r"(a0), "r"(a1), "r"(a2), "r"(a3), "r"(b0), "r"(b1))

// Static scratch (allocations forbidden).
__device__ float g_bufA[33554432];
__device__ float g_bufB[33554432];
__device__ float g_bufW[9043968];  // 276 nodes * 32768 floats (frag-packed hi|lo)

// ---------------------------------------------------------------------------
// First conv: non-overlapping 4x4 patches -> 64 ch + ReLU.
// ---------------------------------------------------------------------------
__global__ void __launch_bounds__(256) first_conv(
    const float* __restrict__ in, const float* __restrict__ fw,
    const float* __restrict__ bias, float* __restrict__ out) {
    __shared__ float sIn[16 * 17];
    __shared__ float sW[1024];
    __shared__ float sB[64];
    const int tid = threadIdx.x;
    for (int j = tid; j < 1024; j += 256) sW[j] = fw[j];
    if (tid < 64) sB[tid] = bias[tid];
    const int P0 = blockIdx.x * 16;
    if (tid < 64) {
        const int pix = tid >> 2, p = tid & 3;
        const int P = P0 + pix, b = P >> 12, x = (P >> 6) & 63, y = P & 63;
        float4 v = *reinterpret_cast<const float4*>(
            in + ((size_t)(b * 256 + 4 * x + p)) * 256 + 4 * y);
        sIn[pix * 17 + p * 4 + 0] = v.x;
        sIn[pix * 17 + p * 4 + 1] = v.y;
        sIn[pix * 17 + p * 4 + 2] = v.z;
        sIn[pix * 17 + p * 4 + 3] = v.w;
    }
    __syncthreads();
    const int c = tid & 63, pq = tid >> 6;
    float acc[4] = {sB[c], sB[c], sB[c], sB[c]};
#pragma unroll
    for (int i = 0; i < 16; i++) {
        const float w = sW[i * 64 + c];
#pragma unroll
        for (int j = 0; j < 4; j++) acc[j] += sIn[(pq * 4 + j) * 17 + i] * w;
    }
#pragma unroll
    for (int j = 0; j < 4; j++)
        out[(size_t)(P0 + pq * 4 + j) * 64 + c] = fmaxf(acc[j], 0.0f);
}

// ---------------------------------------------------------------------------
// W prep: per node, pack W into mma fragment order, tf32 hi/lo split.
// ---------------------------------------------------------------------------
__global__ void __launch_bounds__(256) prep_w(
    const float* __restrict__ f1, const float* __restrict__ f2,
    const float* __restrict__ f3, const float* __restrict__ f4,
    const float* __restrict__ f5, const float* __restrict__ f6,
    float* __restrict__ wt) {
    const int nb = blockIdx.x;  // 0..275
    const float* src;
    int local;
    if (nb < 4)        { src = f1; local = nb; }
    else if (nb < 20)  { src = f2; local = nb - 4; }
    else if (nb < 84)  { src = f3; local = nb - 20; }
    else if (nb < 148) { src = f4; local = nb - 84; }
    else if (nb < 212) { src = f5; local = nb - 148; }
    else               { src = f6; local = nb - 212; }
    src += (size_t)local * 16384;
    float* dst = wt + (size_t)nb * 32768;
    for (int o = threadIdx.x; o < 32768; o += 256) {
        const int p = o >> 14, rem = o & 16383;
        const int sg = rem >> 9, rem2 = rem & 511;
        const int ntp = rem2 >> 7, lane = (rem2 >> 2) & 31, j = o & 3;
        const int tig = lane & 3, grp = lane >> 2;
        const int nt = 2 * ntp + (j >> 1);
        const int k = sg * 8 + tig + (j & 1) * 4;
        const int n = nt * 8 + grp;
        const float w = src[k * 64 + n];
        const float hi = uaf(tf32u(w));
        dst[o] = p ? uaf(tf32u(w - hi)) : hi;
    }
}

// ---------------------------------------------------------------------------
// Tensor node conv via mma.sync m16n8k8 tf32, 3-split.
// Block 128m x 64n, warps 4m x 2n, warp tile 32x32 (2 m16 x 4 n8).
// A smem FRAGMENT-PACKED (R13).  B staged via cp.async (register-free
// GMEM->SMEM verbatim copy of the frag-packed image) — removes the 16-reg
// B prefetch buffer that was forcing spills under (256,2).
// ---------------------------------------------------------------------------
template <int NU, int NP, int HO>
__global__ void __launch_bounds__(256, 2) node_mma(
    const float* __restrict__ in, const float* __restrict__ wfr,
    const float* __restrict__ bias, float* __restrict__ out) {
    constexpr int C = 64, HI = 2 * HO, WI = 2 * HO, WO = HO;
    constexpr int M = 128 * HO * WO;
    constexpr int BUF4 = 2048;  // A float4s per stage buffer (2 planes x 1024)

    extern __shared__ float smem[];
    float4* s4 = reinterpret_cast<float4*>(smem);   // A: 2 * BUF4
    float4* sB4 = s4 + 2 * BUF4;                    // B: 2 * 1024
    const int tid = threadIdx.x;
    const int lane = tid & 31, warp = tid >> 5;
    const int wm = warp & 3, wn = warp >> 2;
    const int g = lane >> 2, tig = lane & 3;

    const int node = blockIdx.y;
    const int u = node / NU, v = node % NU;
    const int pu = (NP < NU) ? (u >> 1) : u;
    const int pv = (NP < NU) ? (v >> 1) : v;
    const float* inN = in + (size_t)(pu * NP + pv) * 128 * HI * WI * C;
    const float* bN = bias + (size_t)node * 64;
    const float4* wN4 = reinterpret_cast<const float4*>(wfr + (size_t)node * 32768);
    const int m0 = blockIdx.x * 128;

    // ---- A staging geometry (thread owns 4m x 4k) ----
    const int mg = tid >> 3, kslot = tid & 7;
    unsigned aoff[4];
#pragma unroll
    for (int i = 0; i < 4; i++) {
        const int m = m0 + mg * 4 + i;
        const int b = m / (HO * WO);
        const int hw = m - b * HO * WO;
        const int h = hw / WO, w = hw - h * WO;
        aoff[i] = (unsigned)((((b * HI + 2 * h) * WI + 2 * w) * C) + kslot * 4);
    }
    float4 aR[4];
    auto LDGA = [&](int s) {
        const int x = s >> 2, y = (s >> 1) & 1, cb = (s & 1) * 32;
        const unsigned soff = (unsigned)((x * WI + y) * C + cb);
#pragma unroll
        for (int i = 0; i < 4; i++)
            aR[i] = *reinterpret_cast<const float4*>(inN + aoff[i] + soff);
    };

    const int sgW = kslot >> 1;
    const int jW = ((mg >> 1) & 1) + 2 * (kslot & 1);
    const int mtileW = mg >> 2;
    const int lpBase = 16 * (mg & 1);
    auto STSA = [&](int buf) {
        float* base = smem + buf * BUF4 * 4;  // scalar view
#pragma unroll
        for (int i = 0; i < 4; i++) {
            const float vals[4] = {(&aR[i].x)[0], (&aR[i].x)[1],
                                   (&aR[i].x)[2], (&aR[i].x)[3]};
#pragma unroll
            for (int e = 0; e < 4; e++) {
                const int lp = lpBase + 4 * i + e;
                const int lsw = lp ^ sgW ^ (((lp >> 4) & 1) << 2);
                const int f4i = sgW * 256 + mtileW * 32 + lsw;
                const float x = vals[e];
                const float h = uaf(tf32u(x));
                base[f4i * 4 + jW] = h;
                base[(1024 + f4i) * 4 + jW] = uaf(tf32u(x - h));
            }
        }
    };

    // ---- B staging: cp.async verbatim copy, layout [sg4][pl2][off128] ----
    const int plB = tid >> 7, offB = tid & 127;
    const uint32_t sBu = s2u(sB4);
    auto CPB = [&](int s, int buf) {
#pragma unroll
        for (int j = 0; j < 4; j++)
            cpasync16(sBu + (buf * 1024 + j * 256 + plB * 128 + offB) * 16,
                      wN4 + plB * 4096 + (4 * s + j) * 128 + offB);
        CP_COMMIT();
    };

    float c[2][4][4];
#pragma unroll
    for (int mt = 0; mt < 2; mt++)
#pragma unroll
        for (int nt = 0; nt < 4; nt++)
#pragma unroll
            for (int j = 0; j < 4; j++) c[mt][nt][j] = 0.0f;

    const int Lc = lane ^ (((lane >> 4) & 1) << 2);

    CPB(0, 0);
    LDGA(0);
    STSA(0);
    CP_WAIT0();
    __syncthreads();

#pragma unroll 1
    for (int s = 0; s < 8; s++) {
        if (s < 7) { LDGA(s + 1); CPB(s + 1, (s + 1) & 1); }
        const float4* Ab = s4 + (s & 1) * BUF4;
        const float4* Bb = sB4 + (s & 1) * 1024;
#pragma unroll
        for (int s8 = 0; s8 < 4; s8++) {
            const int boff = s8 * 256 + wn * 64 + lane;
            const float4 bh0 = Bb[boff];
            const float4 bh1 = Bb[boff + 32];
            const float4 bl0 = Bb[boff + 128];
            const float4 bl1 = Bb[boff + 160];
            const int fb = s8 * 256 + (Lc ^ s8);
#pragma unroll
            for (int mt = 0; mt < 2; mt++) {
                const float4 h4 = Ab[fb + (wm * 2 + mt) * 32];
                const float4 l4 = Ab[1024 + fb + (wm * 2 + mt) * 32];
                const uint32_t ah0 = fau(h4.x), ah1 = fau(h4.y);
                const uint32_t ah2 = fau(h4.z), ah3 = fau(h4.w);
                const uint32_t al0 = fau(l4.x), al1 = fau(l4.y);
                const uint32_t al2 = fau(l4.z), al3 = fau(l4.w);
#pragma unroll
                for (int nt = 0; nt < 4; nt++) {
                    const float4 h = (nt >> 1) ? bh1 : bh0;
                    const float4 l = (nt >> 1) ? bl1 : bl0;
                    uint32_t b0h, b1h, b0l, b1l;
                    if (nt & 1) {
                        b0h = fau(h.z); b1h = fau(h.w);
                        b0l = fau(l.z); b1l = fau(l.w);
                    } else {
                        b0h = fau(h.x); b1h = fau(h.y);
                        b0l = fau(l.x); b1l = fau(l.y);
                    }
                    MMA_TF32(c[mt][nt], ah0, ah1, ah2, ah3, b0h, b1h);
                    MMA_TF32(c[mt][nt], al0, al1, al2, al3, b0h, b1h);
                    MMA_TF32(c[mt][nt], ah0, ah1, ah2, ah3, b0l, b1l);
                }
            }
        }
        if (s < 7) { STSA((s + 1) & 1); CP_WAIT0(); }
        __syncthreads();
    }

    // ---- epilogue: bias + ReLU, float2 stores ----
#pragma unroll
    for (int mt = 0; mt < 2; mt++) {
#pragma unroll
        for (int nt = 0; nt < 4; nt++) {
            const int n0 = wn * 32 + nt * 8 + 2 * tig;
            const float2 bb = *reinterpret_cast<const float2*>(bN + n0);
            const int me = m0 + wm * 32 + mt * 16 + g;
            float* pe = out + ((size_t)node * M + me) * 64 + n0;
            float* po = pe + 8 * 64;
            *reinterpret_cast<float2*>(pe) = make_float2(
                fmaxf(c[mt][nt][0] + bb.x, 0.0f), fmaxf(c[mt][nt][1] + bb.y, 0.0f));
            *reinterpret_cast<float2*>(po) = make_float2(
                fmaxf(c[mt][nt][2] + bb.x, 0.0f), fmaxf(c[mt][nt][3] + bb.y, 0.0f));
        }
    }
}

// ---------------------------------------------------------------------------
// Decode: per node out[u,v,b,r,k] = sum_c feats[u,v,b,c]*Wd[u,v,r,c,k].
// ---------------------------------------------------------------------------
__global__ void __launch_bounds__(256) decode(
    const float* __restrict__ feats, const float* __restrict__ Wd,
    float* __restrict__ out) {
    extern __shared__ float dsm[];
    float* sF = dsm;
    float* sWd = dsm + 8192;
    const int tid = threadIdx.x;
    const int node = blockIdx.x, u = node >> 3, v = node & 7;
    const float* fN = feats + (size_t)node * 8192;
    const float* wN = Wd + (size_t)node * 8192;
#pragma unroll
    for (int j = 0; j < 8; j++) {
        const int f4 = tid + j * 256;
        reinterpret_cast<float4*>(sF)[f4] = reinterpret_cast<const float4*>(fN)[f4];
        reinterpret_cast<float4*>(sWd)[f4] = reinterpret_cast<const float4*>(wN)[f4];
    }
    __syncthreads();
    const int bg = tid >> 4, ng = tid & 15, rr = ng >> 3, kk0 = (ng & 7) * 8;
    float acc[8][8];
#pragma unroll
    for (int i = 0; i < 8; i++)
#pragma unroll
        for (int j = 0; j < 8; j++) acc[i][j] = 0.0f;
#pragma unroll 4
    for (int k = 0; k < 64; k++) {
        const float4 w0 = *reinterpret_cast<const float4*>(sWd + rr * 4096 + k * 64 + kk0);
        const float4 w1 = *reinterpret_cast<const float4*>(sWd + rr * 4096 + k * 64 + kk0 + 4);
        const float wv[8] = {w0.x, w0.y, w0.z, w0.w, w1.x, w1.y, w1.z, w1.w};
#pragma unroll
        for (int i = 0; i < 8; i++) {
            const float a = sF[(bg * 8 + i) * 64 + k];
#pragma unroll
            for (int j = 0; j < 8; j++) acc[i][j] += a * wv[j];
        }
    }
    const int ou = ng & 7;
#pragma unroll
    for (int i = 0; i < 8; i++) {
        const int b = bg * 8 + i;
#pragma unroll
        for (int j = 0; j < 8; j++)
            out[(((size_t)b * 64 + u * 8 + ou) * 64 + (v * 8 + j)) * 2 + rr] = acc[i][j];
    }
}

// ---------------------------------------------------------------------------
extern "C" void kernel_launch(void* const* d_in, const int* in_sizes, int n_in,
                              void* d_out, int out_size) {
    const float* in_data = (const float*)d_in[0];
    const float* in_filter = (const float*)d_in[1];
    const float* in_bias = (const float*)d_in[2];
    const float* f[6];
    const float* bb[6];
    for (int l = 0; l < 6; l++) {
        f[l] = (const float*)d_in[3 + 2 * l];
        bb[l] = (const float*)d_in[4 + 2 * l];
    }
    const float* Wd = (const float*)d_in[15];
    float* out = (float*)d_out;

    float *A, *B, *Wt;
    cudaGetSymbolAddress((void**)&A, g_bufA);
    cudaGetSymbolAddress((void**)&B, g_bufB);
    cudaGetSymbolAddress((void**)&Wt, g_bufW);

    constexpr int SMB = (4096 + 2048) * 16;  // 98,304 B (A 64K + B 32K)
    cudaFuncSetAttribute(node_mma<2, 1, 32>, cudaFuncAttributeMaxDynamicSharedMemorySize, SMB);
    cudaFuncSetAttribute(node_mma<4, 2, 16>, cudaFuncAttributeMaxDynamicSharedMemorySize, SMB);
    cudaFuncSetAttribute(node_mma<8, 4, 8>, cudaFuncAttributeMaxDynamicSharedMemorySize, SMB);
    cudaFuncSetAttribute(node_mma<8, 8, 4>, cudaFuncAttributeMaxDynamicSharedMemorySize, SMB);
    cudaFuncSetAttribute(node_mma<8, 8, 2>, cudaFuncAttributeMaxDynamicSharedMemorySize, SMB);
    cudaFuncSetAttribute(node_mma<8, 8, 1>, cudaFuncAttributeMaxDynamicSharedMemorySize, SMB);
    cudaFuncSetAttribute(decode, cudaFuncAttributeMaxDynamicSharedMemorySize, 65536);

    prep_w<<<276, 256>>>(f[0], f[1], f[2], f[3], f[4], f[5], Wt);
    first_conv<<<32768, 256>>>(in_data, in_filter, in_bias, A);
    node_mma<2, 1, 32><<<dim3(1024, 4), 256, SMB>>>(A, Wt + (size_t)0 * 32768, bb[0], B);
    node_mma<4, 2, 16><<<dim3(256, 16), 256, SMB>>>(B, Wt + (size_t)4 * 32768, bb[1], A);
    node_mma<8, 4, 8><<<dim3(64, 64), 256, SMB>>>(A, Wt + (size_t)20 * 32768, bb[2], B);
    node_mma<8, 8, 4><<<dim3(16, 64), 256, SMB>>>(B, Wt + (size_t)84 * 32768, bb[3], A);
    node_mma<8, 8, 2><<<dim3(4, 64), 256, SMB>>>(A, Wt + (size_t)148 * 32768, bb[4], B);
    node_mma<8, 8, 1><<<dim3(1, 64), 256, SMB>>>(B, Wt + (size_t)212 * 32768, bb[5], A);
    decode<<<64, 256, 65536>>>(A, Wd, out);
}